// round 17
// baseline (speedup 1.0000x reference)
#include <cuda_runtime.h>
#include <math.h>

// ---------------------------------------------------------------------------
// Persistent 2-layer LSTM, fp32, f32x2 FMA, SMEM weights.
// R16: batch-quad threads (4 batch/thread), unified 8-group decomposition:
//   layer0: 4 col-quarters x 2 K-halves;  layer1: 2 col-halves x 4 K-quarters.
//   Per thread: KLEN=256, 12 padded cols, 24 f32x2 accs, LDS:FFMA2 = 1:8.
// ---------------------------------------------------------------------------

#define Bsz   256
#define Tm    512
#define FUTN  16
#define TT    528
#define Hd    512
#define HB    (Hd * Bsz)
#define N0    49
#define N1    99
#define NBLK  (N0 + N1)
#define NTHR  512

#define SMEM_BYTES (37000 * 4)

__device__ float    g_h0[2 * HB];
__device__ float    g_h1[2 * HB];
__device__ float    g_xT[Tm * Bsz];
__device__ unsigned g_count;
__device__ unsigned g_gen;

typedef unsigned long long ull;

__device__ __forceinline__ void ffma2(ull& a, ull w, ull h) {
    asm("fma.rn.f32x2 %0, %1, %2, %0;" : "+l"(a) : "l"(w), "l"(h));
}
__device__ __forceinline__ ull pack2(float x, float y) {
    ull r; asm("mov.b64 %0, {%1, %2};" : "=l"(r) : "f"(x), "f"(y)); return r;
}
__device__ __forceinline__ float2 unpack2(ull v) {
    float2 r; asm("mov.b64 {%0, %1}, %2;" : "=f"(r.x), "=f"(r.y) : "l"(v)); return r;
}
__device__ __forceinline__ float sigf(float x) { return 1.0f / (1.0f + expf(-x)); }

__device__ __forceinline__ void gsync(unsigned target) {
    __syncthreads();
    if (threadIdx.x == 0) {
        __threadfence();
        if (atomicAdd(&g_count, 1u) == (unsigned)(NBLK - 1)) {
            atomicExch(&g_count, 0u);
            __threadfence();
            atomicExch(&g_gen, target);
        } else {
            volatile unsigned* vg = &g_gen;
            while (*vg != target) { }
            __threadfence();
        }
    }
    __syncthreads();
}

// ---- 256-long dot, 12 cols x 4 batch: acc[b*6+q] += W[k][2q:2q+2]*h[k][b] --
template <int RS>
__device__ __forceinline__ void dotq(ull* acc, const float* wr,
                                     const float4* __restrict__ hp) {
    constexpr int KLEN = 256, U = 4;
    float4 hbuf[U];
#pragma unroll
    for (int uu = 0; uu < U; uu++) hbuf[uu] = __ldcg(hp + uu * (Bsz / 4));
#pragma unroll 1
    for (int k0 = 0; k0 < KLEN; k0 += U) {
        float4 hn[U];
        if (k0 + U < KLEN) {
#pragma unroll
            for (int uu = 0; uu < U; uu++)
                hn[uu] = __ldcg(hp + (k0 + U + uu) * (Bsz / 4));
        }
#pragma unroll
        for (int uu = 0; uu < U; uu++) {
            float4 h = hbuf[uu];
            ull hb0 = pack2(h.x, h.x), hb1 = pack2(h.y, h.y);
            ull hb2 = pack2(h.z, h.z), hb3 = pack2(h.w, h.w);
            ulonglong2 w01 = *(const ulonglong2*)(wr);      // cols 0-3
            ulonglong2 w23 = *(const ulonglong2*)(wr + 4);  // cols 4-7
            ulonglong2 w45 = *(const ulonglong2*)(wr + 8);  // cols 8-11
            ffma2(acc[0],  w01.x, hb0); ffma2(acc[1],  w01.y, hb0);
            ffma2(acc[6],  w01.x, hb1); ffma2(acc[7],  w01.y, hb1);
            ffma2(acc[12], w01.x, hb2); ffma2(acc[13], w01.y, hb2);
            ffma2(acc[18], w01.x, hb3); ffma2(acc[19], w01.y, hb3);
            ffma2(acc[2],  w23.x, hb0); ffma2(acc[3],  w23.y, hb0);
            ffma2(acc[8],  w23.x, hb1); ffma2(acc[9],  w23.y, hb1);
            ffma2(acc[14], w23.x, hb2); ffma2(acc[15], w23.y, hb2);
            ffma2(acc[20], w23.x, hb3); ffma2(acc[21], w23.y, hb3);
            ffma2(acc[4],  w45.x, hb0); ffma2(acc[5],  w45.y, hb0);
            ffma2(acc[10], w45.x, hb1); ffma2(acc[11], w45.y, hb1);
            ffma2(acc[16], w45.x, hb2); ffma2(acc[17], w45.y, hb2);
            ffma2(acc[22], w45.x, hb3); ffma2(acc[23], w45.y, hb3);
            wr += RS;
        }
#pragma unroll
        for (int uu = 0; uu < U; uu++) hbuf[uu] = hn[uu];
    }
}

// ---- phased merge of K-group partials into gbuf ----------------------------
template <int GW, int NGK>
__device__ __forceinline__ void merge(const ull* acc, float* __restrict__ gbuf,
                                      int grpc, int gk, int b0) {
#pragma unroll
    for (int p = 0; p < NGK; p++) {
        if (gk == p) {
#pragma unroll
            for (int b = 0; b < 4; b++) {
                float* r = gbuf + (b0 + b) * GW + grpc * 12;
                if (p == 0) {
#pragma unroll
                    for (int q = 0; q < 6; q++) ((ull*)r)[q] = acc[b * 6 + q];
                } else {
#pragma unroll
                    for (int q = 0; q < 6; q++) {
                        float2 v = unpack2(acc[b * 6 + q]);
                        r[2 * q]     += v.x;
                        r[2 * q + 1] += v.y;
                    }
                }
            }
        }
        __syncthreads();
    }
}

// ---- cell update: 8 groups split the NH units ------------------------------
template <int NH, int NCG, int GW, bool L1F>
__device__ __forceinline__ void cellup(const float* __restrict__ gbuf,
                                       const float* __restrict__ wlinv,
                                       float* __restrict__ hout,
                                       float* __restrict__ out, int t,
                                       float* cst, int u0, int gid, int b0) {
    constexpr int NU8 = (NH + 7) / 8;
    const int u_lo = (NH * gid) / 8, u_hi = (NH * (gid + 1)) / 8;
    float sum[4] = {0.0f, 0.0f, 0.0f, 0.0f};
#pragma unroll
    for (int jj = 0; jj < NU8; jj++) {
        int j = u_lo + jj;
        if (j < u_hi) {
            const int ci = j,          di = (ci / NCG) * 12 + ci % NCG;
            const int cf = NH + j,     df = (cf / NCG) * 12 + cf % NCG;
            const int cg = 2 * NH + j, dg = (cg / NCG) * 12 + cg % NCG;
            const int co = 3 * NH + j, dw = (co / NCG) * 12 + co % NCG;
            float hv[4];
#pragma unroll
            for (int b = 0; b < 4; b++) {
                const float* r = gbuf + (b0 + b) * GW;
                float ig = sigf(r[di]);
                float fg = sigf(r[df]);
                float gg = tanhf(r[dg]);
                float og = sigf(r[dw]);
                float c  = fg * cst[4 * jj + b] + ig * gg;
                cst[4 * jj + b] = c;
                hv[b] = og * tanhf(c);
                if (L1F) sum[b] += wlinv[j] * hv[b];
            }
            __stcg((float4*)&hout[(u0 + j) * Bsz + b0],
                   make_float4(hv[0], hv[1], hv[2], hv[3]));
        }
    }
    if (L1F && u_hi > u_lo) {
#pragma unroll
        for (int b = 0; b < 4; b++) atomicAdd(out + (b0 + b) * TT + t, sum[b]);
    }
}

// ---------------- layer 0 step ----------------------------------------------
template <int NH>
__device__ __forceinline__ void l0_step(const float* __restrict__ ws,
                                        const float* __restrict__ biasv,
                                        const float* __restrict__ wihv,
                                        float* __restrict__ gbuf,
                                        const float* __restrict__ hprev,
                                        float* __restrict__ hout,
                                        float4 xv, float* cst,
                                        int u0, int grpc, int gk, int b0) {
    constexpr int RS = 48, GW = 48, NCG = NH;
    ull acc[24];
    if (gk == 0) {
        const ull* bh = (const ull*)(biasv + grpc * 12);
        const ull* ax = (const ull*)(wihv + grpc * 12);
        ull xb0 = pack2(xv.x, xv.x), xb1 = pack2(xv.y, xv.y);
        ull xb2 = pack2(xv.z, xv.z), xb3 = pack2(xv.w, xv.w);
#pragma unroll
        for (int q = 0; q < 6; q++) {
            ull b = bh[q], w = ax[q];
            acc[q] = b;      ffma2(acc[q],      w, xb0);
            acc[6 + q] = b;  ffma2(acc[6 + q],  w, xb1);
            acc[12 + q] = b; ffma2(acc[12 + q], w, xb2);
            acc[18 + q] = b; ffma2(acc[18 + q], w, xb3);
        }
    } else {
        ull z = pack2(0.0f, 0.0f);
#pragma unroll
        for (int p = 0; p < 24; p++) acc[p] = z;
    }
    dotq<RS>(acc, ws + gk * 256 * RS + grpc * 12,
             (const float4*)(hprev + gk * 256 * Bsz + b0));
    merge<GW, 2>(acc, gbuf, grpc, gk, b0);
    cellup<NH, NCG, GW, false>(gbuf, (const float*)0, hout, (float*)0, 0,
                               cst, u0, gk * 4 + grpc, b0);
}

// ---------------- layer 1 step ----------------------------------------------
template <int NH>
__device__ __forceinline__ void l1_step(const float* __restrict__ ws,
                                        const float* __restrict__ biasv,
                                        const float* __restrict__ wlinv,
                                        float* __restrict__ gbuf,
                                        const float* __restrict__ h0cur,
                                        const float* __restrict__ h1prev,
                                        float* __restrict__ hout,
                                        float* __restrict__ out, int t,
                                        float* cst, int u0, int grpc, int gk, int b0) {
    constexpr int RS = 24, GW = 24, NCG = 2 * NH;
    ull acc[24];
    if (gk == 0) {
        const ull* bh = (const ull*)(biasv + grpc * 12);
#pragma unroll
        for (int q = 0; q < 6; q++) {
            ull b = bh[q];
            acc[q] = b; acc[6 + q] = b; acc[12 + q] = b; acc[18 + q] = b;
        }
    } else {
        ull z = pack2(0.0f, 0.0f);
#pragma unroll
        for (int p = 0; p < 24; p++) acc[p] = z;
    }
    const float* hsrc = (gk < 2) ? h0cur : h1prev;
    const int koff = (gk & 1) * 256;
    dotq<RS>(acc, ws + gk * 256 * RS + grpc * 12,
             (const float4*)(hsrc + koff * Bsz + b0));
    merge<GW, 4>(acc, gbuf, grpc, gk, b0);
    cellup<NH, NCG, GW, true>(gbuf, wlinv, hout, out, t,
                              cst, u0, gk * 2 + grpc, b0);
}

// ---------------- per-CTA loops (barrier sequences identical) ---------------
template <int NH>
__device__ __noinline__ void run_l0(const float* ws, const float* biasv, const float* wihv,
                                    float* gbuf, float* out, int u0, unsigned gen0,
                                    int grpc, int gk, int b0) {
    constexpr int NU8 = (NH + 7) / 8;
    float cst[4 * NU8];
#pragma unroll
    for (int j = 0; j < 4 * NU8; j++) cst[j] = 0.0f;
    unsigned nbar = 2;
    for (int s = 0; s <= Tm; s++) {
        if (s < Tm) {
            float4 xv = *(const float4*)&g_xT[s * Bsz + b0];
            l0_step<NH>(ws, biasv, wihv, gbuf,
                        g_h0 + ((unsigned)(s + 1) & 1u) * HB,
                        g_h0 + ((unsigned)s & 1u) * HB,
                        xv, cst, u0, grpc, gk, b0);
        }
        gsync(gen0 + nbar); nbar++;
    }
    for (int f = 0; f < FUTN; f++) {
        int t = Tm + f;
        float4 xv;
        xv.x = __ldcg(&out[(b0 + 0) * TT + (t - 1)]);
        xv.y = __ldcg(&out[(b0 + 1) * TT + (t - 1)]);
        xv.z = __ldcg(&out[(b0 + 2) * TT + (t - 1)]);
        xv.w = __ldcg(&out[(b0 + 3) * TT + (t - 1)]);
        l0_step<NH>(ws, biasv, wihv, gbuf,
                    g_h0 + ((unsigned)(t + 1) & 1u) * HB,
                    g_h0 + ((unsigned)t & 1u) * HB,
                    xv, cst, u0, grpc, gk, b0);
        gsync(gen0 + nbar); nbar++;
        gsync(gen0 + nbar); nbar++;
    }
}

template <int NH>
__device__ __noinline__ void run_l1(const float* ws, const float* biasv, const float* wlinv,
                                    float* gbuf, float* out, int u0, unsigned gen0,
                                    int grpc, int gk, int b0) {
    constexpr int NU8 = (NH + 7) / 8;
    float cst[4 * NU8];
#pragma unroll
    for (int j = 0; j < 4 * NU8; j++) cst[j] = 0.0f;
    unsigned nbar = 2;
    for (int s = 0; s <= Tm; s++) {
        if (s >= 1) {
            int t = s - 1;
            l1_step<NH>(ws, biasv, wlinv, gbuf,
                        g_h0 + ((unsigned)t & 1u) * HB,
                        g_h1 + ((unsigned)(t + 1) & 1u) * HB,
                        g_h1 + ((unsigned)t & 1u) * HB,
                        out, t, cst, u0, grpc, gk, b0);
        }
        gsync(gen0 + nbar); nbar++;
    }
    for (int f = 0; f < FUTN; f++) {
        int t = Tm + f;
        gsync(gen0 + nbar); nbar++;
        l1_step<NH>(ws, biasv, wlinv, gbuf,
                    g_h0 + ((unsigned)t & 1u) * HB,
                    g_h1 + ((unsigned)(t + 1) & 1u) * HB,
                    g_h1 + ((unsigned)t & 1u) * HB,
                    out, t, cst, u0, grpc, gk, b0);
        gsync(gen0 + nbar); nbar++;
    }
}

// ---------------------------------------------------------------------------
__global__ void __launch_bounds__(NTHR, 1)
lstm_persistent_kernel(const float* __restrict__ x,
                       const float* __restrict__ Wih0, const float* __restrict__ Whh0,
                       const float* __restrict__ bih0, const float* __restrict__ bhh0,
                       const float* __restrict__ Wih1, const float* __restrict__ Whh1,
                       const float* __restrict__ bih1, const float* __restrict__ bhh1,
                       const float* __restrict__ Wlin, const float* __restrict__ blin,
                       float* __restrict__ out) {
    extern __shared__ float smem[];
    const int tid  = threadIdx.x;
    const int bid  = blockIdx.x;
    const int l    = tid & 63;           // batch quad: b0 = 4*l
    const int gidx = tid >> 6;           // 8 groups
    const int b0   = 4 * l;

    __shared__ unsigned s_gen0;
    if (tid == 0) s_gen0 = *((volatile unsigned*)&g_gen);
    __syncthreads();
    const unsigned gen0 = s_gen0;

    const bool isL0 = (bid < N0);
    const int  gi   = isL0 ? bid : bid - N0;
    int u0, u1;
    if (isL0) { u0 = (Hd * gi) / N0; u1 = (Hd * (gi + 1)) / N0; }
    else      { u0 = (Hd * gi) / N1; u1 = (Hd * (gi + 1)) / N1; }
    const int nh  = u1 - u0;
    const int nc  = 4 * nh;
    // group split: layer0: 4 col-quarters x 2 K-halves; layer1: 2 x 4
    const int grpc = isL0 ? (gidx & 3) : (gidx & 1);
    const int gk   = isL0 ? (gidx >> 2) : (gidx >> 1);
    const int ncg  = isL0 ? nh : 2 * nh;   // cols per col-group (pad to 12)
    const int rs   = isL0 ? 48 : 24;
    const int K    = isL0 ? Hd : 2 * Hd;

    float* ws    = smem;              // [K][rs], col-group g at offset g*12
    float* biasv = smem + K * rs;     // [rs]
    float* auxv  = biasv + rs;        // layer0: Wih0 [rs]; layer1: Wlin [nh]
    float* gbuf  = auxv + rs;         // [Bsz][rs]

    // ---- one-time weight staging (padded cols -> 0) -----------------------
    for (int dc = 0; dc < rs; dc++) {
        int grp = dc / 12, lc = dc - grp * 12;
        if (lc < ncg) {
            int c = grp * ncg + lc;
            int gate = c / nh, j = c - gate * nh;
            int row = gate * Hd + u0 + j;
            if (isL0) {
                for (int k = tid; k < Hd; k += NTHR) ws[k * rs + dc] = Whh0[row * Hd + k];
                if (tid == 0) { biasv[dc] = bih0[row] + bhh0[row]; auxv[dc] = Wih0[row]; }
            } else {
                for (int k = tid; k < Hd; k += NTHR) {
                    ws[k * rs + dc]        = Wih1[row * Hd + k];
                    ws[(Hd + k) * rs + dc] = Whh1[row * Hd + k];
                }
                if (tid == 0) biasv[dc] = bih1[row] + bhh1[row];
            }
        } else {
            for (int k = tid; k < K; k += NTHR) ws[k * rs + dc] = 0.0f;
            if (tid == 0) { biasv[dc] = 0.0f; if (isL0) auxv[dc] = 0.0f; }
        }
    }
    if (!isL0 && tid == 0) for (int j = 0; j < nh; j++) auxv[j] = Wlin[u0 + j];

    // ---- per-launch global init (idempotent across graph replays) ---------
    const float bl = blin[0];
    for (int i = bid * NTHR + tid; i < Bsz * TT; i += NBLK * NTHR) __stcg(&out[i], bl);
    for (int i = bid * NTHR + tid; i < 2 * HB; i += NBLK * NTHR) {
        __stcg(&g_h0[i], 0.0f);
        __stcg(&g_h1[i], 0.0f);
    }
    for (int i = bid * NTHR + tid; i < Bsz * Tm; i += NBLK * NTHR) {
        int b = i / Tm, t = i - b * Tm;
        __stcg(&g_xT[t * Bsz + b], x[i]);
    }
    gsync(gen0 + 1);

    if (isL0) {
        if (nh == 11) run_l0<11>(ws, biasv, auxv, gbuf, out, u0, gen0, grpc, gk, b0);
        else          run_l0<10>(ws, biasv, auxv, gbuf, out, u0, gen0, grpc, gk, b0);
    } else {
        if (nh == 6)  run_l1<6 >(ws, biasv, auxv, gbuf, out, u0, gen0, grpc, gk, b0);
        else          run_l1<5 >(ws, biasv, auxv, gbuf, out, u0, gen0, grpc, gk, b0);
    }
}

// ---------------------------------------------------------------------------
extern "C" void kernel_launch(void* const* d_in, const int* in_sizes, int n_in,
                              void* d_out, int out_size) {
    (void)in_sizes; (void)n_in; (void)out_size;
    const float* x    = (const float*)d_in[0];
    const float* Wih0 = (const float*)d_in[1];
    const float* Whh0 = (const float*)d_in[2];
    const float* bih0 = (const float*)d_in[3];
    const float* bhh0 = (const float*)d_in[4];
    const float* Wih1 = (const float*)d_in[5];
    const float* Whh1 = (const float*)d_in[6];
    const float* bih1 = (const float*)d_in[7];
    const float* bhh1 = (const float*)d_in[8];
    const float* Wlin = (const float*)d_in[9];
    const float* blin = (const float*)d_in[10];
    float* out = (float*)d_out;

    cudaFuncSetAttribute(lstm_persistent_kernel,
                         cudaFuncAttributeMaxDynamicSharedMemorySize, SMEM_BYTES);

    lstm_persistent_kernel<<<NBLK, NTHR, SMEM_BYTES>>>(
        x, Wih0, Whh0, bih0, bhh0, Wih1, Whh1, bih1, bhh1, Wlin, blin, out);
}